// round 13
// baseline (speedup 1.0000x reference)
#include <cuda_runtime.h>
#include <cuda_fp16.h>

// ---------------------------------------------------------------------------
// EnhancedQuanvolution via warp-level HMMA, fp16 A, fp16 hi/lo W (2 products).
// R13: rolling 3-deep LDG window carried ACROSS the MMA section (last 3 loads
// of each chunk fetch the next chunk's first 3 tiles, hiding DRAM latency
// under HMMA work). Chunk loop unrolled x3 with rotated register bindings so
// window slots stay statically indexed. B fragments loaded JIT in MMA loop.
// No L2 prefetch (R12 regression). block=448 (14 warps), grid=147.
// ---------------------------------------------------------------------------

static constexpr int THREADS   = 448;
static constexpr int IMG_BLK   = 448;
static constexpr int NCHUNK    = 14;
static constexpr int FROW      = 144;              // 64 k * 2B + 16B pad
static constexpr int FBUF      = 32 * FROW;        // 4608 B per warp
static constexpr int WCHUNK    = 2 * 16 * FROW;    // 4608 B per chunk (Whi+Wlo)
static constexpr int OFF_FEAT  = NCHUNK * WCHUNK;  // 64512
static constexpr int OFF_BIAS  = OFF_FEAT + 14 * FBUF;  // 129024
static constexpr int SMEM_REQ  = OFF_BIAS + 64;

__device__ __align__(16) unsigned char gWp[NCHUNK * WCHUNK];

__global__ void prep_w(const float* __restrict__ W) {
    int i = blockIdx.x * blockDim.x + threadIdx.x;   // 14*16*64 = 14336
    if (i >= NCHUNK * 16 * 64) return;
    int c = i >> 10, n = (i >> 6) & 15, k = i & 63;
    float w = (n < 10 && k < 56) ? W[n * 784 + c * 56 + k] : 0.f;
    __half h = __float2half_rn(w);
    __half l = __float2half_rn(w - __half2float(h));
    unsigned char* base = gWp + c * WCHUNK;
    *(__half*)(base + n * FROW + k * 2) = h;
    *(__half*)(base + 16 * FROW + n * FROW + k * 2) = l;
}

__device__ __forceinline__ void cp_async16(unsigned dst, const void* src) {
    asm volatile("cp.async.cg.shared.global [%0], [%1], 16;" :: "r"(dst), "l"(src) : "memory");
}
__device__ __forceinline__ unsigned lds32(unsigned a) {
    unsigned v; asm volatile("ld.shared.b32 %0, [%1];" : "=r"(v) : "r"(a)); return v;
}
__device__ __forceinline__ void sts128(unsigned a, unsigned r0, unsigned r1,
                                       unsigned r2, unsigned r3) {
    asm volatile("st.shared.v4.b32 [%0], {%1,%2,%3,%4};"
                 :: "r"(a), "r"(r0), "r"(r1), "r"(r2), "r"(r3) : "memory");
}
__device__ __forceinline__ void ldsm4(unsigned* r, unsigned a) {
    asm volatile("ldmatrix.sync.aligned.m8n8.x4.shared.b16 {%0,%1,%2,%3}, [%4];"
                 : "=r"(r[0]), "=r"(r[1]), "=r"(r[2]), "=r"(r[3]) : "r"(a));
}
__device__ __forceinline__ void mma16816(float* d, const unsigned* a,
                                         unsigned b0, unsigned b1) {
    asm volatile("mma.sync.aligned.m16n8k16.row.col.f32.f16.f16.f32 "
                 "{%0,%1,%2,%3}, {%4,%5,%6,%7}, {%8,%9}, {%0,%1,%2,%3};"
                 : "+f"(d[0]), "+f"(d[1]), "+f"(d[2]), "+f"(d[3])
                 : "r"(a[0]), "r"(a[1]), "r"(a[2]), "r"(a[3]), "r"(b0), "r"(b1));
}
__device__ __forceinline__ unsigned pack_h2(float a, float b) {
    unsigned r;
    asm("cvt.rn.f16x2.f32 %0, %1, %2;" : "=r"(r) : "f"(b), "f"(a));
    return r;
}

struct P { float4 q0, q1; };

__global__ __launch_bounds__(THREADS, 1)
void quanv_hmma(const float* __restrict__ x, const float* __restrict__ bias,
                float* __restrict__ out, int batch) {
    extern __shared__ unsigned char sm[];
    const unsigned smb = (unsigned)__cvta_generic_to_shared(sm);
    float* bias_sh = (float*)(sm + OFF_BIAS);

    const int tid = threadIdx.x, lane = tid & 31, wid = tid >> 5;
    const float4 z4 = make_float4(0.f, 0.f, 0.f, 0.f);

    // ---- init: copy pre-split W, zero feat buffers, bias ---------------------
#pragma unroll
    for (int r = 0; r < 9; r++) {
        int off = (tid + r * THREADS) * 16;
        cp_async16(smb + off, gWp + off);
    }
    asm volatile("cp.async.commit_group;" ::: "memory");
#pragma unroll
    for (int r = 0; r < 9; r++) {
        int off = OFF_FEAT + (tid + r * THREADS) * 16;
        *(float4*)(sm + off) = z4;
    }
    if (tid < 10) bias_sh[tid] = bias[tid];
    asm volatile("cp.async.wait_group 0;" ::: "memory");
    __syncthreads();

    const int wimg = blockIdx.x * IMG_BLK + wid * 32;
    const unsigned fbuf = smb + OFF_FEAT + wid * FBUF;

    float d[2][2][4];
#pragma unroll
    for (int m = 0; m < 2; m++)
#pragma unroll
        for (int nt = 0; nt < 2; nt++)
#pragma unroll
            for (int e = 0; e < 4; e++) d[m][nt][e] = 0.f;

    const unsigned rowsel = (lane & 7) + 8 * ((lane >> 3) & 1);
    const unsigned koff = ((lane >> 4) & 1) * 16;

    auto ld_t = [&](P& p, int c, int t) {
        int n = lane + 32 * t;
        int img = n / 7, j = n - img * 7;
        p.q0 = z4; p.q1 = z4;
        if (wimg + img < batch) {
            const float* px = x + (size_t)(wimg + img) * 784 + c * 56 + j * 4;
            p.q0 = *(const float4*)px;          // row 2c
            p.q1 = *(const float4*)(px + 28);   // row 2c+1
        }
    };
    auto do_t = [&](const P& p, int t) {
        float f0 = __cosf(p.q0.x), f1 = f0 * __cosf(p.q0.y);
        float f2 = f1 * __cosf(p.q1.x), f3 = f2 * __cosf(p.q1.y);
        float g0 = __cosf(p.q0.z), g1 = g0 * __cosf(p.q0.w);
        float g2 = g1 * __cosf(p.q1.z), g3 = g2 * __cosf(p.q1.w);
        int n = lane + 32 * t;
        int img = n / 7, j = n - img * 7;
        unsigned sa = fbuf + img * FROW + j * 16;
        sts128(sa, pack_h2(f0, f1), pack_h2(f2, f3),
                   pack_h2(g0, g1), pack_h2(g2, g3));
    };

    // one full chunk: consume window (c: t0,t1,t2 in a,b,e), refill across
    // the MMA boundary with (c+1: t0,t1,t2) landing in b,e,a.
    auto body = [&](int c, P& a, P& b, P& e) {
        do_t(a, 0); ld_t(a, c, 3);
        do_t(b, 1); ld_t(b, c, 4);
        do_t(e, 2); ld_t(e, c, 5);
        do_t(a, 3); ld_t(a, c, 6);
        bool nx = (c + 1 < NCHUNK);
        do_t(b, 4); if (nx) ld_t(b, c + 1, 0);
        do_t(e, 5); if (nx) ld_t(e, c + 1, 1);
        do_t(a, 6); if (nx) ld_t(a, c + 1, 2);
        __syncwarp();

        // A fragments (both M tiles)
        unsigned ah[2][4][4];
#pragma unroll
        for (int m = 0; m < 2; m++)
#pragma unroll
            for (int T = 0; T < 4; T++)
                ldsm4(ah[m][T], fbuf + (16 * m + rowsel) * FROW + T * 32 + koff);

        // B fragments JIT + MMA
        const unsigned wb = smb + c * WCHUNK;
#pragma unroll
        for (int nt = 0; nt < 2; nt++)
#pragma unroll
            for (int T = 0; T < 4; T++) {
                unsigned ba = wb + (nt * 8 + (lane >> 2)) * FROW + T * 32 + (lane & 3) * 4;
                unsigned bh0 = lds32(ba), bh1 = lds32(ba + 16);
                unsigned bl0 = lds32(ba + 16 * FROW), bl1 = lds32(ba + 16 * FROW + 16);
                mma16816(d[0][nt], ah[0][T], bh0, bh1);
                mma16816(d[0][nt], ah[0][T], bl0, bl1);
                mma16816(d[1][nt], ah[1][T], bh0, bh1);
                mma16816(d[1][nt], ah[1][T], bl0, bl1);
            }
        __syncwarp();
    };

    // prologue: window = chunk 0, t0..2
    P a, b, e;
    ld_t(a, 0, 0); ld_t(b, 0, 1); ld_t(e, 0, 2);

#pragma unroll 1
    for (int cc = 0; cc < 12; cc += 3) {
        body(cc,     a, b, e);
        body(cc + 1, b, e, a);
        body(cc + 2, e, a, b);
    }
    body(12, a, b, e);
    body(13, b, e, a);

    // ---- epilogue: bias + log_softmax (4-lane groups per image) ---------------
    const int q = lane & 3;
    const float b0 = bias_sh[2 * q], b1 = bias_sh[2 * q + 1];
    const float b8 = bias_sh[8], b9 = bias_sh[9];
#pragma unroll
    for (int m = 0; m < 2; m++)
#pragma unroll
        for (int h = 0; h < 2; h++) {
            int img = wimg + 16 * m + 8 * h + (lane >> 2);
            float v0 = d[m][0][2 * h] + b0;
            float v1 = d[m][0][2 * h + 1] + b1;
            float v2 = (q == 0) ? d[m][1][2 * h] + b8 : -1e30f;
            float v3 = (q == 0) ? d[m][1][2 * h + 1] + b9 : -1e30f;
            float mx = fmaxf(fmaxf(v0, v1), fmaxf(v2, v3));
            mx = fmaxf(mx, __shfl_xor_sync(0xffffffffu, mx, 1));
            mx = fmaxf(mx, __shfl_xor_sync(0xffffffffu, mx, 2));
            float s = __expf(v0 - mx) + __expf(v1 - mx);
            if (q == 0) s += __expf(v2 - mx) + __expf(v3 - mx);
            s += __shfl_xor_sync(0xffffffffu, s, 1);
            s += __shfl_xor_sync(0xffffffffu, s, 2);
            float lse = mx + __logf(s);
            if (img < batch) {
                float* op = out + (size_t)img * 10;
                *(float2*)(op + 2 * q) = make_float2(v0 - lse, v1 - lse);
                if (q == 0) *(float2*)(op + 8) = make_float2(v2 - lse, v3 - lse);
            }
        }
}

extern "C" void kernel_launch(void* const* d_in, const int* in_sizes, int n_in,
                              void* d_out, int out_size) {
    const float* x = (const float*)d_in[0];   // (B,1,28,28) fp32
    const float* W = (const float*)d_in[1];   // (10,784)    fp32
    const float* b = (const float*)d_in[2];   // (10,)       fp32
    float* out = (float*)d_out;               // (B,10)      fp32

    int batch = in_sizes[0] / 784;

    prep_w<<<(NCHUNK * 16 * 64 + 255) / 256, 256>>>(W);

    int grid = (batch + IMG_BLK - 1) / IMG_BLK;
    cudaFuncSetAttribute(quanv_hmma, cudaFuncAttributeMaxDynamicSharedMemorySize, SMEM_REQ);
    quanv_hmma<<<grid, THREADS, SMEM_REQ>>>(x, b, out, batch);
}

// round 14
// speedup vs baseline: 1.0040x; 1.0040x over previous
#include <cuda_runtime.h>
#include <cuda_fp16.h>

// ---------------------------------------------------------------------------
// EnhancedQuanvolution via warp-level HMMA, fp16 A, fp16 hi/lo W (2 products).
// R13: rolling 3-deep LDG window carried ACROSS the MMA section (last 3 loads
// of each chunk fetch the next chunk's first 3 tiles, hiding DRAM latency
// under HMMA work). Chunk loop unrolled x3 with rotated register bindings so
// window slots stay statically indexed. B fragments loaded JIT in MMA loop.
// No L2 prefetch (R12 regression). block=448 (14 warps), grid=147.
// ---------------------------------------------------------------------------

static constexpr int THREADS   = 448;
static constexpr int IMG_BLK   = 448;
static constexpr int NCHUNK    = 14;
static constexpr int FROW      = 144;              // 64 k * 2B + 16B pad
static constexpr int FBUF      = 32 * FROW;        // 4608 B per warp
static constexpr int WCHUNK    = 2 * 16 * FROW;    // 4608 B per chunk (Whi+Wlo)
static constexpr int OFF_FEAT  = NCHUNK * WCHUNK;  // 64512
static constexpr int OFF_BIAS  = OFF_FEAT + 14 * FBUF;  // 129024
static constexpr int SMEM_REQ  = OFF_BIAS + 64;

__device__ __align__(16) unsigned char gWp[NCHUNK * WCHUNK];

__global__ void prep_w(const float* __restrict__ W) {
    int i = blockIdx.x * blockDim.x + threadIdx.x;   // 14*16*64 = 14336
    if (i >= NCHUNK * 16 * 64) return;
    int c = i >> 10, n = (i >> 6) & 15, k = i & 63;
    float w = (n < 10 && k < 56) ? W[n * 784 + c * 56 + k] : 0.f;
    __half h = __float2half_rn(w);
    __half l = __float2half_rn(w - __half2float(h));
    unsigned char* base = gWp + c * WCHUNK;
    *(__half*)(base + n * FROW + k * 2) = h;
    *(__half*)(base + 16 * FROW + n * FROW + k * 2) = l;
}

__device__ __forceinline__ void cp_async16(unsigned dst, const void* src) {
    asm volatile("cp.async.cg.shared.global [%0], [%1], 16;" :: "r"(dst), "l"(src) : "memory");
}
__device__ __forceinline__ unsigned lds32(unsigned a) {
    unsigned v; asm volatile("ld.shared.b32 %0, [%1];" : "=r"(v) : "r"(a)); return v;
}
__device__ __forceinline__ void sts128(unsigned a, unsigned r0, unsigned r1,
                                       unsigned r2, unsigned r3) {
    asm volatile("st.shared.v4.b32 [%0], {%1,%2,%3,%4};"
                 :: "r"(a), "r"(r0), "r"(r1), "r"(r2), "r"(r3) : "memory");
}
__device__ __forceinline__ void ldsm4(unsigned* r, unsigned a) {
    asm volatile("ldmatrix.sync.aligned.m8n8.x4.shared.b16 {%0,%1,%2,%3}, [%4];"
                 : "=r"(r[0]), "=r"(r[1]), "=r"(r[2]), "=r"(r[3]) : "r"(a));
}
__device__ __forceinline__ void mma16816(float* d, const unsigned* a,
                                         unsigned b0, unsigned b1) {
    asm volatile("mma.sync.aligned.m16n8k16.row.col.f32.f16.f16.f32 "
                 "{%0,%1,%2,%3}, {%4,%5,%6,%7}, {%8,%9}, {%0,%1,%2,%3};"
                 : "+f"(d[0]), "+f"(d[1]), "+f"(d[2]), "+f"(d[3])
                 : "r"(a[0]), "r"(a[1]), "r"(a[2]), "r"(a[3]), "r"(b0), "r"(b1));
}
__device__ __forceinline__ unsigned pack_h2(float a, float b) {
    unsigned r;
    asm("cvt.rn.f16x2.f32 %0, %1, %2;" : "=r"(r) : "f"(b), "f"(a));
    return r;
}

struct P { float4 q0, q1; };

__global__ __launch_bounds__(THREADS, 1)
void quanv_hmma(const float* __restrict__ x, const float* __restrict__ bias,
                float* __restrict__ out, int batch) {
    extern __shared__ unsigned char sm[];
    const unsigned smb = (unsigned)__cvta_generic_to_shared(sm);
    float* bias_sh = (float*)(sm + OFF_BIAS);

    const int tid = threadIdx.x, lane = tid & 31, wid = tid >> 5;
    const float4 z4 = make_float4(0.f, 0.f, 0.f, 0.f);

    // ---- init: copy pre-split W, zero feat buffers, bias ---------------------
#pragma unroll
    for (int r = 0; r < 9; r++) {
        int off = (tid + r * THREADS) * 16;
        cp_async16(smb + off, gWp + off);
    }
    asm volatile("cp.async.commit_group;" ::: "memory");
#pragma unroll
    for (int r = 0; r < 9; r++) {
        int off = OFF_FEAT + (tid + r * THREADS) * 16;
        *(float4*)(sm + off) = z4;
    }
    if (tid < 10) bias_sh[tid] = bias[tid];
    asm volatile("cp.async.wait_group 0;" ::: "memory");
    __syncthreads();

    const int wimg = blockIdx.x * IMG_BLK + wid * 32;
    const unsigned fbuf = smb + OFF_FEAT + wid * FBUF;

    float d[2][2][4];
#pragma unroll
    for (int m = 0; m < 2; m++)
#pragma unroll
        for (int nt = 0; nt < 2; nt++)
#pragma unroll
            for (int e = 0; e < 4; e++) d[m][nt][e] = 0.f;

    const unsigned rowsel = (lane & 7) + 8 * ((lane >> 3) & 1);
    const unsigned koff = ((lane >> 4) & 1) * 16;

    auto ld_t = [&](P& p, int c, int t) {
        int n = lane + 32 * t;
        int img = n / 7, j = n - img * 7;
        p.q0 = z4; p.q1 = z4;
        if (wimg + img < batch) {
            const float* px = x + (size_t)(wimg + img) * 784 + c * 56 + j * 4;
            p.q0 = *(const float4*)px;          // row 2c
            p.q1 = *(const float4*)(px + 28);   // row 2c+1
        }
    };
    auto do_t = [&](const P& p, int t) {
        float f0 = __cosf(p.q0.x), f1 = f0 * __cosf(p.q0.y);
        float f2 = f1 * __cosf(p.q1.x), f3 = f2 * __cosf(p.q1.y);
        float g0 = __cosf(p.q0.z), g1 = g0 * __cosf(p.q0.w);
        float g2 = g1 * __cosf(p.q1.z), g3 = g2 * __cosf(p.q1.w);
        int n = lane + 32 * t;
        int img = n / 7, j = n - img * 7;
        unsigned sa = fbuf + img * FROW + j * 16;
        sts128(sa, pack_h2(f0, f1), pack_h2(f2, f3),
                   pack_h2(g0, g1), pack_h2(g2, g3));
    };

    // one full chunk: consume window (c: t0,t1,t2 in a,b,e), refill across
    // the MMA boundary with (c+1: t0,t1,t2) landing in b,e,a.
    auto body = [&](int c, P& a, P& b, P& e) {
        do_t(a, 0); ld_t(a, c, 3);
        do_t(b, 1); ld_t(b, c, 4);
        do_t(e, 2); ld_t(e, c, 5);
        do_t(a, 3); ld_t(a, c, 6);
        bool nx = (c + 1 < NCHUNK);
        do_t(b, 4); if (nx) ld_t(b, c + 1, 0);
        do_t(e, 5); if (nx) ld_t(e, c + 1, 1);
        do_t(a, 6); if (nx) ld_t(a, c + 1, 2);
        __syncwarp();

        // A fragments (both M tiles)
        unsigned ah[2][4][4];
#pragma unroll
        for (int m = 0; m < 2; m++)
#pragma unroll
            for (int T = 0; T < 4; T++)
                ldsm4(ah[m][T], fbuf + (16 * m + rowsel) * FROW + T * 32 + koff);

        // B fragments JIT + MMA
        const unsigned wb = smb + c * WCHUNK;
#pragma unroll
        for (int nt = 0; nt < 2; nt++)
#pragma unroll
            for (int T = 0; T < 4; T++) {
                unsigned ba = wb + (nt * 8 + (lane >> 2)) * FROW + T * 32 + (lane & 3) * 4;
                unsigned bh0 = lds32(ba), bh1 = lds32(ba + 16);
                unsigned bl0 = lds32(ba + 16 * FROW), bl1 = lds32(ba + 16 * FROW + 16);
                mma16816(d[0][nt], ah[0][T], bh0, bh1);
                mma16816(d[0][nt], ah[0][T], bl0, bl1);
                mma16816(d[1][nt], ah[1][T], bh0, bh1);
                mma16816(d[1][nt], ah[1][T], bl0, bl1);
            }
        __syncwarp();
    };

    // prologue: window = chunk 0, t0..2
    P a, b, e;
    ld_t(a, 0, 0); ld_t(b, 0, 1); ld_t(e, 0, 2);

#pragma unroll 1
    for (int cc = 0; cc < 12; cc += 3) {
        body(cc,     a, b, e);
        body(cc + 1, b, e, a);
        body(cc + 2, e, a, b);
    }
    body(12, a, b, e);
    body(13, b, e, a);

    // ---- epilogue: bias + log_softmax (4-lane groups per image) ---------------
    const int q = lane & 3;
    const float b0 = bias_sh[2 * q], b1 = bias_sh[2 * q + 1];
    const float b8 = bias_sh[8], b9 = bias_sh[9];
#pragma unroll
    for (int m = 0; m < 2; m++)
#pragma unroll
        for (int h = 0; h < 2; h++) {
            int img = wimg + 16 * m + 8 * h + (lane >> 2);
            float v0 = d[m][0][2 * h] + b0;
            float v1 = d[m][0][2 * h + 1] + b1;
            float v2 = (q == 0) ? d[m][1][2 * h] + b8 : -1e30f;
            float v3 = (q == 0) ? d[m][1][2 * h + 1] + b9 : -1e30f;
            float mx = fmaxf(fmaxf(v0, v1), fmaxf(v2, v3));
            mx = fmaxf(mx, __shfl_xor_sync(0xffffffffu, mx, 1));
            mx = fmaxf(mx, __shfl_xor_sync(0xffffffffu, mx, 2));
            float s = __expf(v0 - mx) + __expf(v1 - mx);
            if (q == 0) s += __expf(v2 - mx) + __expf(v3 - mx);
            s += __shfl_xor_sync(0xffffffffu, s, 1);
            s += __shfl_xor_sync(0xffffffffu, s, 2);
            float lse = mx + __logf(s);
            if (img < batch) {
                float* op = out + (size_t)img * 10;
                *(float2*)(op + 2 * q) = make_float2(v0 - lse, v1 - lse);
                if (q == 0) *(float2*)(op + 8) = make_float2(v2 - lse, v3 - lse);
            }
        }
}

extern "C" void kernel_launch(void* const* d_in, const int* in_sizes, int n_in,
                              void* d_out, int out_size) {
    const float* x = (const float*)d_in[0];   // (B,1,28,28) fp32
    const float* W = (const float*)d_in[1];   // (10,784)    fp32
    const float* b = (const float*)d_in[2];   // (10,)       fp32
    float* out = (float*)d_out;               // (B,10)      fp32

    int batch = in_sizes[0] / 784;

    prep_w<<<(NCHUNK * 16 * 64 + 255) / 256, 256>>>(W);

    int grid = (batch + IMG_BLK - 1) / IMG_BLK;
    cudaFuncSetAttribute(quanv_hmma, cudaFuncAttributeMaxDynamicSharedMemorySize, SMEM_REQ);
    quanv_hmma<<<grid, THREADS, SMEM_REQ>>>(x, b, out, batch);
}

// round 15
// speedup vs baseline: 1.0317x; 1.0276x over previous
#include <cuda_runtime.h>
#include <cuda_fp16.h>

// ---------------------------------------------------------------------------
// EnhancedQuanvolution via warp-level HMMA, fp16 A, fp16 hi/lo W (2 products).
// R15: per-warp cp.async pixel staging (single 7168B buffer, two 112B-stride
// planes) gives ~7KB/warp of in-flight DRAM traffic; feats are computed from
// smem (LDS) so no 600-cycle LDG sits in the dependency chain. Next chunk's
// cp.asyncs issue right after the feat reads and fly under the MMA section.
// Structure otherwise identical to R11 (best: 45.6us).
// block=448 (14 warps), grid=147.
// ---------------------------------------------------------------------------

static constexpr int THREADS   = 448;
static constexpr int IMG_BLK   = 448;
static constexpr int NCHUNK    = 14;
static constexpr int FROW      = 144;              // 64 k * 2B + 16B pad
static constexpr int FBUF      = 32 * FROW;        // 4608 B per warp (feats)
static constexpr int WCHUNK    = 2 * 16 * FROW;    // 4608 B per chunk (Whi+Wlo)
static constexpr int PIX_PLANE = 32 * 28;          // floats (112B per img row)
static constexpr int PIX_WARP  = 2 * PIX_PLANE;    // 1792 floats = 7168 B
static constexpr int OFF_FEAT  = NCHUNK * WCHUNK;               // 64512
static constexpr int OFF_PIX   = OFF_FEAT + 14 * FBUF;          // 129024
static constexpr int OFF_BIAS  = OFF_PIX + 14 * PIX_WARP * 4;   // 229376
static constexpr int SMEM_REQ  = OFF_BIAS + 64;                 // 229440

__device__ __align__(16) unsigned char gWp[NCHUNK * WCHUNK];

__global__ void prep_w(const float* __restrict__ W) {
    int i = blockIdx.x * blockDim.x + threadIdx.x;   // 14*16*64 = 14336
    if (i >= NCHUNK * 16 * 64) return;
    int c = i >> 10, n = (i >> 6) & 15, k = i & 63;
    float w = (n < 10 && k < 56) ? W[n * 784 + c * 56 + k] : 0.f;
    __half h = __float2half_rn(w);
    __half l = __float2half_rn(w - __half2float(h));
    unsigned char* base = gWp + c * WCHUNK;
    *(__half*)(base + n * FROW + k * 2) = h;
    *(__half*)(base + 16 * FROW + n * FROW + k * 2) = l;
}

__device__ __forceinline__ void cp_async16(unsigned dst, const void* src) {
    asm volatile("cp.async.cg.shared.global [%0], [%1], 16;" :: "r"(dst), "l"(src) : "memory");
}
__device__ __forceinline__ unsigned lds32(unsigned a) {
    unsigned v; asm volatile("ld.shared.b32 %0, [%1];" : "=r"(v) : "r"(a)); return v;
}
__device__ __forceinline__ float4 lds128(unsigned a) {
    float4 v;
    asm volatile("ld.shared.v4.f32 {%0,%1,%2,%3}, [%4];"
                 : "=f"(v.x), "=f"(v.y), "=f"(v.z), "=f"(v.w) : "r"(a));
    return v;
}
__device__ __forceinline__ void sts128(unsigned a, unsigned r0, unsigned r1,
                                       unsigned r2, unsigned r3) {
    asm volatile("st.shared.v4.b32 [%0], {%1,%2,%3,%4};"
                 :: "r"(a), "r"(r0), "r"(r1), "r"(r2), "r"(r3) : "memory");
}
__device__ __forceinline__ void ldsm4(unsigned* r, unsigned a) {
    asm volatile("ldmatrix.sync.aligned.m8n8.x4.shared.b16 {%0,%1,%2,%3}, [%4];"
                 : "=r"(r[0]), "=r"(r[1]), "=r"(r[2]), "=r"(r[3]) : "r"(a));
}
__device__ __forceinline__ void mma16816(float* d, const unsigned* a,
                                         unsigned b0, unsigned b1) {
    asm volatile("mma.sync.aligned.m16n8k16.row.col.f32.f16.f16.f32 "
                 "{%0,%1,%2,%3}, {%4,%5,%6,%7}, {%8,%9}, {%0,%1,%2,%3};"
                 : "+f"(d[0]), "+f"(d[1]), "+f"(d[2]), "+f"(d[3])
                 : "r"(a[0]), "r"(a[1]), "r"(a[2]), "r"(a[3]), "r"(b0), "r"(b1));
}
__device__ __forceinline__ unsigned pack_h2(float a, float b) {
    unsigned r;
    asm("cvt.rn.f16x2.f32 %0, %1, %2;" : "=r"(r) : "f"(b), "f"(a));
    return r;
}

__global__ __launch_bounds__(THREADS, 1)
void quanv_hmma(const float* __restrict__ x, const float* __restrict__ bias,
                float* __restrict__ out, int batch) {
    extern __shared__ unsigned char sm[];
    const unsigned smb = (unsigned)__cvta_generic_to_shared(sm);
    float* bias_sh = (float*)(sm + OFF_BIAS);

    const int tid = threadIdx.x, lane = tid & 31, wid = tid >> 5;
    const float4 z4 = make_float4(0.f, 0.f, 0.f, 0.f);

    // ---- init: copy pre-split W, zero feat buffers, bias ---------------------
#pragma unroll
    for (int r = 0; r < 9; r++) {
        int off = (tid + r * THREADS) * 16;
        cp_async16(smb + off, gWp + off);
    }
    asm volatile("cp.async.commit_group;" ::: "memory");
#pragma unroll
    for (int r = 0; r < 9; r++) {
        int off = OFF_FEAT + (tid + r * THREADS) * 16;
        *(float4*)(sm + off) = z4;
    }
    if (tid < 10) bias_sh[tid] = bias[tid];
    asm volatile("cp.async.wait_group 0;" ::: "memory");
    __syncthreads();

    const int wimg = blockIdx.x * IMG_BLK + wid * 32;
    const unsigned fbuf = smb + OFF_FEAT + wid * FBUF;
    const unsigned pix0 = smb + OFF_PIX + wid * PIX_WARP * 4;     // plane 0
    const unsigned pix1 = pix0 + PIX_PLANE * 4;                   // plane 1

    // stage chunk c into this warp's pixel buffer (both rows, coalesced)
    auto stage = [&](int c) {
#pragma unroll
        for (int k = 0; k < 14; k++) {
            int n = lane + 32 * k;            // 0..447 = 32 imgs * 14 float4
            int img = n / 14;
            int j = n - img * 14;             // float4 index in 224B row-pair
            if (wimg + img < batch) {
                const float* src = x + (size_t)(wimg + img) * 784 + c * 56 + j * 4;
                unsigned dst = ((j < 7) ? pix0 : pix1)
                             + (img * 28 + ((j < 7) ? j : j - 7) * 4) * 4;
                cp_async16(dst, src);
            }
        }
        asm volatile("cp.async.commit_group;" ::: "memory");
    };

    stage(0);   // prologue

    float d[2][2][4];
#pragma unroll
    for (int m = 0; m < 2; m++)
#pragma unroll
        for (int nt = 0; nt < 2; nt++)
#pragma unroll
            for (int e = 0; e < 4; e++) d[m][nt][e] = 0.f;

    const unsigned rowsel = (lane & 7) + 8 * ((lane >> 3) & 1);
    const unsigned koff = ((lane >> 4) & 1) * 16;
    const bool img_ok = (wimg + lane) < batch;

#pragma unroll 1
    for (int c = 0; c < NCHUNK; c++) {
        asm volatile("cp.async.wait_group 0;" ::: "memory");
        __syncwarp();

        // ---- feats from smem pixels (lane = its own image) -------------------
        if (img_ok) {
            const unsigned r0 = pix0 + lane * 112;
            const unsigned r1 = pix1 + lane * 112;
#pragma unroll
            for (int v = 0; v < 7; v++) {
                float4 q0 = lds128(r0 + v * 16);
                float4 q1 = lds128(r1 + v * 16);
                float f0 = __cosf(q0.x), f1 = f0 * __cosf(q0.y);
                float f2 = f1 * __cosf(q1.x), f3 = f2 * __cosf(q1.y);
                float g0 = __cosf(q0.z), g1 = g0 * __cosf(q0.w);
                float g2 = g1 * __cosf(q1.z), g3 = g2 * __cosf(q1.w);
                sts128(fbuf + lane * FROW + v * 16,
                       pack_h2(f0, f1), pack_h2(f2, f3),
                       pack_h2(g0, g1), pack_h2(g2, g3));
            }
        }
        __syncwarp();   // pixel reads + feat stores complete warp-wide

        // ---- launch next chunk's pixel loads (flies under MMA below) ---------
        if (c + 1 < NCHUNK) stage(c + 1);

        // ---- A fragments ------------------------------------------------------
        unsigned ah[2][4][4];
#pragma unroll
        for (int m = 0; m < 2; m++)
#pragma unroll
            for (int T = 0; T < 4; T++)
                ldsm4(ah[m][T], fbuf + (16 * m + rowsel) * FROW + T * 32 + koff);

        // ---- B fragments JIT + MMA ---------------------------------------------
        const unsigned wb = smb + c * WCHUNK;
#pragma unroll
        for (int nt = 0; nt < 2; nt++)
#pragma unroll
            for (int T = 0; T < 4; T++) {
                unsigned ba = wb + (nt * 8 + (lane >> 2)) * FROW + T * 32 + (lane & 3) * 4;
                unsigned bh0 = lds32(ba), bh1 = lds32(ba + 16);
                unsigned bl0 = lds32(ba + 16 * FROW), bl1 = lds32(ba + 16 * FROW + 16);
                mma16816(d[0][nt], ah[0][T], bh0, bh1);
                mma16816(d[0][nt], ah[0][T], bl0, bl1);
                mma16816(d[1][nt], ah[1][T], bh0, bh1);
                mma16816(d[1][nt], ah[1][T], bl0, bl1);
            }
    }

    // ---- epilogue: bias + log_softmax (4-lane groups per image) ---------------
    const int q = lane & 3;
    const float b0 = bias_sh[2 * q], b1 = bias_sh[2 * q + 1];
    const float b8 = bias_sh[8], b9 = bias_sh[9];
#pragma unroll
    for (int m = 0; m < 2; m++)
#pragma unroll
        for (int h = 0; h < 2; h++) {
            int img = wimg + 16 * m + 8 * h + (lane >> 2);
            float v0 = d[m][0][2 * h] + b0;
            float v1 = d[m][0][2 * h + 1] + b1;
            float v2 = (q == 0) ? d[m][1][2 * h] + b8 : -1e30f;
            float v3 = (q == 0) ? d[m][1][2 * h + 1] + b9 : -1e30f;
            float mx = fmaxf(fmaxf(v0, v1), fmaxf(v2, v3));
            mx = fmaxf(mx, __shfl_xor_sync(0xffffffffu, mx, 1));
            mx = fmaxf(mx, __shfl_xor_sync(0xffffffffu, mx, 2));
            float s = __expf(v0 - mx) + __expf(v1 - mx);
            if (q == 0) s += __expf(v2 - mx) + __expf(v3 - mx);
            s += __shfl_xor_sync(0xffffffffu, s, 1);
            s += __shfl_xor_sync(0xffffffffu, s, 2);
            float lse = mx + __logf(s);
            if (img < batch) {
                float* op = out + (size_t)img * 10;
                *(float2*)(op + 2 * q) = make_float2(v0 - lse, v1 - lse);
                if (q == 0) *(float2*)(op + 8) = make_float2(v2 - lse, v3 - lse);
            }
        }
}

extern "C" void kernel_launch(void* const* d_in, const int* in_sizes, int n_in,
                              void* d_out, int out_size) {
    const float* x = (const float*)d_in[0];   // (B,1,28,28) fp32
    const float* W = (const float*)d_in[1];   // (10,784)    fp32
    const float* b = (const float*)d_in[2];   // (10,)       fp32
    float* out = (float*)d_out;               // (B,10)      fp32

    int batch = in_sizes[0] / 784;

    prep_w<<<(NCHUNK * 16 * 64 + 255) / 256, 256>>>(W);

    int grid = (batch + IMG_BLK - 1) / IMG_BLK;
    cudaFuncSetAttribute(quanv_hmma, cudaFuncAttributeMaxDynamicSharedMemorySize, SMEM_REQ);
    quanv_hmma<<<grid, THREADS, SMEM_REQ>>>(x, b, out, batch);
}

// round 16
// speedup vs baseline: 1.0928x; 1.0592x over previous
#include <cuda_runtime.h>
#include <cuda_fp16.h>

// ---------------------------------------------------------------------------
// EnhancedQuanvolution via warp-level HMMA. R16 = R11 structure (direct LDG
// feats, per-warp feat smem, ldmatrix A + LDS B, m16n8k16 f16 HMMA) with a
// SINGLE fp16 W product (W-lo dropped; measured A-rounding aggregate 3.2e-5
// predicts total ~6e-5 << 1e-3). Halves HMMA + B-LDS per chunk and W smem.
// block=448 (14 warps), grid=147.
// ---------------------------------------------------------------------------

static constexpr int THREADS   = 448;
static constexpr int IMG_BLK   = 448;
static constexpr int NCHUNK    = 14;
static constexpr int FROW      = 144;              // 64 k * 2B + 16B pad
static constexpr int FBUF      = 32 * FROW;        // 4608 B per warp (fp16 feats)
static constexpr int WCHUNK    = 16 * FROW;        // 2304 B per chunk (fp16 W)
static constexpr int OFF_FEAT  = NCHUNK * WCHUNK;  // 32256
static constexpr int OFF_BIAS  = OFF_FEAT + 14 * FBUF;  // 96768
static constexpr int SMEM_REQ  = OFF_BIAS + 64;

__device__ __align__(16) unsigned char gWp[NCHUNK * WCHUNK];

// fp16 W (RN), zero-padded n>=10, k>=56.
__global__ void prep_w(const float* __restrict__ W) {
    int i = blockIdx.x * blockDim.x + threadIdx.x;   // 14*16*64 = 14336
    if (i >= NCHUNK * 16 * 64) return;
    int c = i >> 10, n = (i >> 6) & 15, k = i & 63;
    float w = (n < 10 && k < 56) ? W[n * 784 + c * 56 + k] : 0.f;
    *(__half*)(gWp + c * WCHUNK + n * FROW + k * 2) = __float2half_rn(w);
}

__device__ __forceinline__ void cp_async16(unsigned dst, const void* src) {
    asm volatile("cp.async.cg.shared.global [%0], [%1], 16;" :: "r"(dst), "l"(src) : "memory");
}
__device__ __forceinline__ unsigned lds32(unsigned a) {
    unsigned v; asm volatile("ld.shared.b32 %0, [%1];" : "=r"(v) : "r"(a)); return v;
}
__device__ __forceinline__ void sts128(unsigned a, unsigned r0, unsigned r1,
                                       unsigned r2, unsigned r3) {
    asm volatile("st.shared.v4.b32 [%0], {%1,%2,%3,%4};"
                 :: "r"(a), "r"(r0), "r"(r1), "r"(r2), "r"(r3) : "memory");
}
__device__ __forceinline__ void ldsm4(unsigned* r, unsigned a) {
    asm volatile("ldmatrix.sync.aligned.m8n8.x4.shared.b16 {%0,%1,%2,%3}, [%4];"
                 : "=r"(r[0]), "=r"(r[1]), "=r"(r[2]), "=r"(r[3]) : "r"(a));
}
__device__ __forceinline__ void mma16816(float* d, const unsigned* a,
                                         unsigned b0, unsigned b1) {
    asm volatile("mma.sync.aligned.m16n8k16.row.col.f32.f16.f16.f32 "
                 "{%0,%1,%2,%3}, {%4,%5,%6,%7}, {%8,%9}, {%0,%1,%2,%3};"
                 : "+f"(d[0]), "+f"(d[1]), "+f"(d[2]), "+f"(d[3])
                 : "r"(a[0]), "r"(a[1]), "r"(a[2]), "r"(a[3]), "r"(b0), "r"(b1));
}
__device__ __forceinline__ unsigned pack_h2(float a, float b) {
    unsigned r;
    asm("cvt.rn.f16x2.f32 %0, %1, %2;" : "=r"(r) : "f"(b), "f"(a));
    return r;
}

__global__ __launch_bounds__(THREADS, 1)
void quanv_hmma(const float* __restrict__ x, const float* __restrict__ bias,
                float* __restrict__ out, int batch) {
    extern __shared__ unsigned char sm[];
    const unsigned smb = (unsigned)__cvta_generic_to_shared(sm);
    float* bias_sh = (float*)(sm + OFF_BIAS);

    const int tid = threadIdx.x, lane = tid & 31, wid = tid >> 5;
    const float4 z4 = make_float4(0.f, 0.f, 0.f, 0.f);

    // ---- init: copy fp16 W (cp.async), zero feat buffers, bias ---------------
#pragma unroll
    for (int r = 0; r < 5; r++) {                 // 5*448*16 = 35840 >= 32256
        int off = (tid + r * THREADS) * 16;
        if (off < OFF_FEAT) cp_async16(smb + off, gWp + off);
    }
    asm volatile("cp.async.commit_group;" ::: "memory");
#pragma unroll
    for (int r = 0; r < 9; r++) {                 // 9*448*16 = 64512
        int off = OFF_FEAT + (tid + r * THREADS) * 16;
        *(float4*)(sm + off) = z4;
    }
    if (tid < 10) bias_sh[tid] = bias[tid];
    asm volatile("cp.async.wait_group 0;" ::: "memory");
    __syncthreads();

    const int wimg = blockIdx.x * IMG_BLK + wid * 32;
    const unsigned fbuf = smb + OFF_FEAT + wid * FBUF;

    float d[2][2][4];
#pragma unroll
    for (int m = 0; m < 2; m++)
#pragma unroll
        for (int nt = 0; nt < 2; nt++)
#pragma unroll
            for (int e = 0; e < 4; e++) d[m][nt][e] = 0.f;

    const unsigned rowsel = (lane & 7) + 8 * ((lane >> 3) & 1);
    const unsigned koff = ((lane >> 4) & 1) * 16;

#pragma unroll 1
    for (int c = 0; c < NCHUNK; c++) {
        __syncwarp();
        // ---- feats: lane handles 7 (img, col4) positions ----------------------
#pragma unroll
        for (int t = 0; t < 7; t++) {
            int n = lane + 32 * t;               // 0..223 = 32 imgs * 7 float4-cols
            int img = n / 7;
            int j = n - img * 7;                 // float4 col 0..6
            float4 q0 = z4, q1 = z4;
            if (wimg + img < batch) {
                const float* px = x + (size_t)(wimg + img) * 784 + c * 56 + j * 4;
                q0 = *(const float4*)px;          // row 2c
                q1 = *(const float4*)(px + 28);   // row 2c+1
            }
            float f0 = __cosf(q0.x), f1 = f0 * __cosf(q0.y);
            float f2 = f1 * __cosf(q1.x), f3 = f2 * __cosf(q1.y);
            float g0 = __cosf(q0.z), g1 = g0 * __cosf(q0.w);
            float g2 = g1 * __cosf(q1.z), g3 = g2 * __cosf(q1.w);
            unsigned sa = fbuf + img * FROW + j * 16;   // k = 8j..8j+7
            sts128(sa, pack_h2(f0, f1), pack_h2(f2, f3),
                       pack_h2(g0, g1), pack_h2(g2, g3));
        }
        __syncwarp();

        // ---- A fragments -------------------------------------------------------
        unsigned ah[2][4][4];
#pragma unroll
        for (int m = 0; m < 2; m++)
#pragma unroll
            for (int T = 0; T < 4; T++)
                ldsm4(ah[m][T], fbuf + (16 * m + rowsel) * FROW + T * 32 + koff);

        // ---- B fragments JIT + MMA (single fp16 W product) ---------------------
        const unsigned wb = smb + c * WCHUNK;
#pragma unroll
        for (int nt = 0; nt < 2; nt++)
#pragma unroll
            for (int T = 0; T < 4; T++) {
                unsigned ba = wb + (nt * 8 + (lane >> 2)) * FROW + T * 32 + (lane & 3) * 4;
                unsigned b0 = lds32(ba), b1 = lds32(ba + 16);
                mma16816(d[0][nt], ah[0][T], b0, b1);
                mma16816(d[1][nt], ah[1][T], b0, b1);
            }
    }

    // ---- epilogue: bias + log_softmax (4-lane groups per image) ---------------
    const int q = lane & 3;
    const float b0 = bias_sh[2 * q], b1 = bias_sh[2 * q + 1];
    const float b8 = bias_sh[8], b9 = bias_sh[9];
#pragma unroll
    for (int m = 0; m < 2; m++)
#pragma unroll
        for (int h = 0; h < 2; h++) {
            int img = wimg + 16 * m + 8 * h + (lane >> 2);
            float v0 = d[m][0][2 * h] + b0;
            float v1 = d[m][0][2 * h + 1] + b1;
            float v2 = (q == 0) ? d[m][1][2 * h] + b8 : -1e30f;
            float v3 = (q == 0) ? d[m][1][2 * h + 1] + b9 : -1e30f;
            float mx = fmaxf(fmaxf(v0, v1), fmaxf(v2, v3));
            mx = fmaxf(mx, __shfl_xor_sync(0xffffffffu, mx, 1));
            mx = fmaxf(mx, __shfl_xor_sync(0xffffffffu, mx, 2));
            float s = __expf(v0 - mx) + __expf(v1 - mx);
            if (q == 0) s += __expf(v2 - mx) + __expf(v3 - mx);
            s += __shfl_xor_sync(0xffffffffu, s, 1);
            s += __shfl_xor_sync(0xffffffffu, s, 2);
            float lse = mx + __logf(s);
            if (img < batch) {
                float* op = out + (size_t)img * 10;
                *(float2*)(op + 2 * q) = make_float2(v0 - lse, v1 - lse);
                if (q == 0) *(float2*)(op + 8) = make_float2(v2 - lse, v3 - lse);
            }
        }
}

extern "C" void kernel_launch(void* const* d_in, const int* in_sizes, int n_in,
                              void* d_out, int out_size) {
    const float* x = (const float*)d_in[0];   // (B,1,28,28) fp32
    const float* W = (const float*)d_in[1];   // (10,784)    fp32
    const float* b = (const float*)d_in[2];   // (10,)       fp32
    float* out = (float*)d_out;               // (B,10)      fp32

    int batch = in_sizes[0] / 784;

    prep_w<<<(NCHUNK * 16 * 64 + 255) / 256, 256>>>(W);

    int grid = (batch + IMG_BLK - 1) / IMG_BLK;
    cudaFuncSetAttribute(quanv_hmma, cudaFuncAttributeMaxDynamicSharedMemorySize, SMEM_REQ);
    quanv_hmma<<<grid, THREADS, SMEM_REQ>>>(x, b, out, batch);
}

// round 17
// speedup vs baseline: 1.1001x; 1.0066x over previous
#include <cuda_runtime.h>
#include <cuda_fp16.h>

// ---------------------------------------------------------------------------
// EnhancedQuanvolution via warp-level HMMA. R16 = R11 structure (direct LDG
// feats, per-warp feat smem, ldmatrix A + LDS B, m16n8k16 f16 HMMA) with a
// SINGLE fp16 W product (W-lo dropped; measured A-rounding aggregate 3.2e-5
// predicts total ~6e-5 << 1e-3). Halves HMMA + B-LDS per chunk and W smem.
// block=448 (14 warps), grid=147.
// ---------------------------------------------------------------------------

static constexpr int THREADS   = 448;
static constexpr int IMG_BLK   = 448;
static constexpr int NCHUNK    = 14;
static constexpr int FROW      = 144;              // 64 k * 2B + 16B pad
static constexpr int FBUF      = 32 * FROW;        // 4608 B per warp (fp16 feats)
static constexpr int WCHUNK    = 16 * FROW;        // 2304 B per chunk (fp16 W)
static constexpr int OFF_FEAT  = NCHUNK * WCHUNK;  // 32256
static constexpr int OFF_BIAS  = OFF_FEAT + 14 * FBUF;  // 96768
static constexpr int SMEM_REQ  = OFF_BIAS + 64;

__device__ __align__(16) unsigned char gWp[NCHUNK * WCHUNK];

// fp16 W (RN), zero-padded n>=10, k>=56.
__global__ void prep_w(const float* __restrict__ W) {
    int i = blockIdx.x * blockDim.x + threadIdx.x;   // 14*16*64 = 14336
    if (i >= NCHUNK * 16 * 64) return;
    int c = i >> 10, n = (i >> 6) & 15, k = i & 63;
    float w = (n < 10 && k < 56) ? W[n * 784 + c * 56 + k] : 0.f;
    *(__half*)(gWp + c * WCHUNK + n * FROW + k * 2) = __float2half_rn(w);
}

__device__ __forceinline__ void cp_async16(unsigned dst, const void* src) {
    asm volatile("cp.async.cg.shared.global [%0], [%1], 16;" :: "r"(dst), "l"(src) : "memory");
}
__device__ __forceinline__ unsigned lds32(unsigned a) {
    unsigned v; asm volatile("ld.shared.b32 %0, [%1];" : "=r"(v) : "r"(a)); return v;
}
__device__ __forceinline__ void sts128(unsigned a, unsigned r0, unsigned r1,
                                       unsigned r2, unsigned r3) {
    asm volatile("st.shared.v4.b32 [%0], {%1,%2,%3,%4};"
                 :: "r"(a), "r"(r0), "r"(r1), "r"(r2), "r"(r3) : "memory");
}
__device__ __forceinline__ void ldsm4(unsigned* r, unsigned a) {
    asm volatile("ldmatrix.sync.aligned.m8n8.x4.shared.b16 {%0,%1,%2,%3}, [%4];"
                 : "=r"(r[0]), "=r"(r[1]), "=r"(r[2]), "=r"(r[3]) : "r"(a));
}
__device__ __forceinline__ void mma16816(float* d, const unsigned* a,
                                         unsigned b0, unsigned b1) {
    asm volatile("mma.sync.aligned.m16n8k16.row.col.f32.f16.f16.f32 "
                 "{%0,%1,%2,%3}, {%4,%5,%6,%7}, {%8,%9}, {%0,%1,%2,%3};"
                 : "+f"(d[0]), "+f"(d[1]), "+f"(d[2]), "+f"(d[3])
                 : "r"(a[0]), "r"(a[1]), "r"(a[2]), "r"(a[3]), "r"(b0), "r"(b1));
}
__device__ __forceinline__ unsigned pack_h2(float a, float b) {
    unsigned r;
    asm("cvt.rn.f16x2.f32 %0, %1, %2;" : "=r"(r) : "f"(b), "f"(a));
    return r;
}

__global__ __launch_bounds__(THREADS, 1)
void quanv_hmma(const float* __restrict__ x, const float* __restrict__ bias,
                float* __restrict__ out, int batch) {
    extern __shared__ unsigned char sm[];
    const unsigned smb = (unsigned)__cvta_generic_to_shared(sm);
    float* bias_sh = (float*)(sm + OFF_BIAS);

    const int tid = threadIdx.x, lane = tid & 31, wid = tid >> 5;
    const float4 z4 = make_float4(0.f, 0.f, 0.f, 0.f);

    // ---- init: copy fp16 W (cp.async), zero feat buffers, bias ---------------
#pragma unroll
    for (int r = 0; r < 5; r++) {                 // 5*448*16 = 35840 >= 32256
        int off = (tid + r * THREADS) * 16;
        if (off < OFF_FEAT) cp_async16(smb + off, gWp + off);
    }
    asm volatile("cp.async.commit_group;" ::: "memory");
#pragma unroll
    for (int r = 0; r < 9; r++) {                 // 9*448*16 = 64512
        int off = OFF_FEAT + (tid + r * THREADS) * 16;
        *(float4*)(sm + off) = z4;
    }
    if (tid < 10) bias_sh[tid] = bias[tid];
    asm volatile("cp.async.wait_group 0;" ::: "memory");
    __syncthreads();

    const int wimg = blockIdx.x * IMG_BLK + wid * 32;
    const unsigned fbuf = smb + OFF_FEAT + wid * FBUF;

    float d[2][2][4];
#pragma unroll
    for (int m = 0; m < 2; m++)
#pragma unroll
        for (int nt = 0; nt < 2; nt++)
#pragma unroll
            for (int e = 0; e < 4; e++) d[m][nt][e] = 0.f;

    const unsigned rowsel = (lane & 7) + 8 * ((lane >> 3) & 1);
    const unsigned koff = ((lane >> 4) & 1) * 16;

#pragma unroll 1
    for (int c = 0; c < NCHUNK; c++) {
        __syncwarp();
        // ---- feats: lane handles 7 (img, col4) positions ----------------------
#pragma unroll
        for (int t = 0; t < 7; t++) {
            int n = lane + 32 * t;               // 0..223 = 32 imgs * 7 float4-cols
            int img = n / 7;
            int j = n - img * 7;                 // float4 col 0..6
            float4 q0 = z4, q1 = z4;
            if (wimg + img < batch) {
                const float* px = x + (size_t)(wimg + img) * 784 + c * 56 + j * 4;
                q0 = *(const float4*)px;          // row 2c
                q1 = *(const float4*)(px + 28);   // row 2c+1
            }
            float f0 = __cosf(q0.x), f1 = f0 * __cosf(q0.y);
            float f2 = f1 * __cosf(q1.x), f3 = f2 * __cosf(q1.y);
            float g0 = __cosf(q0.z), g1 = g0 * __cosf(q0.w);
            float g2 = g1 * __cosf(q1.z), g3 = g2 * __cosf(q1.w);
            unsigned sa = fbuf + img * FROW + j * 16;   // k = 8j..8j+7
            sts128(sa, pack_h2(f0, f1), pack_h2(f2, f3),
                       pack_h2(g0, g1), pack_h2(g2, g3));
        }
        __syncwarp();

        // ---- A fragments -------------------------------------------------------
        unsigned ah[2][4][4];
#pragma unroll
        for (int m = 0; m < 2; m++)
#pragma unroll
            for (int T = 0; T < 4; T++)
                ldsm4(ah[m][T], fbuf + (16 * m + rowsel) * FROW + T * 32 + koff);

        // ---- B fragments JIT + MMA (single fp16 W product) ---------------------
        const unsigned wb = smb + c * WCHUNK;
#pragma unroll
        for (int nt = 0; nt < 2; nt++)
#pragma unroll
            for (int T = 0; T < 4; T++) {
                unsigned ba = wb + (nt * 8 + (lane >> 2)) * FROW + T * 32 + (lane & 3) * 4;
                unsigned b0 = lds32(ba), b1 = lds32(ba + 16);
                mma16816(d[0][nt], ah[0][T], b0, b1);
                mma16816(d[1][nt], ah[1][T], b0, b1);
            }
    }

    // ---- epilogue: bias + log_softmax (4-lane groups per image) ---------------
    const int q = lane & 3;
    const float b0 = bias_sh[2 * q], b1 = bias_sh[2 * q + 1];
    const float b8 = bias_sh[8], b9 = bias_sh[9];
#pragma unroll
    for (int m = 0; m < 2; m++)
#pragma unroll
        for (int h = 0; h < 2; h++) {
            int img = wimg + 16 * m + 8 * h + (lane >> 2);
            float v0 = d[m][0][2 * h] + b0;
            float v1 = d[m][0][2 * h + 1] + b1;
            float v2 = (q == 0) ? d[m][1][2 * h] + b8 : -1e30f;
            float v3 = (q == 0) ? d[m][1][2 * h + 1] + b9 : -1e30f;
            float mx = fmaxf(fmaxf(v0, v1), fmaxf(v2, v3));
            mx = fmaxf(mx, __shfl_xor_sync(0xffffffffu, mx, 1));
            mx = fmaxf(mx, __shfl_xor_sync(0xffffffffu, mx, 2));
            float s = __expf(v0 - mx) + __expf(v1 - mx);
            if (q == 0) s += __expf(v2 - mx) + __expf(v3 - mx);
            s += __shfl_xor_sync(0xffffffffu, s, 1);
            s += __shfl_xor_sync(0xffffffffu, s, 2);
            float lse = mx + __logf(s);
            if (img < batch) {
                float* op = out + (size_t)img * 10;
                *(float2*)(op + 2 * q) = make_float2(v0 - lse, v1 - lse);
                if (q == 0) *(float2*)(op + 8) = make_float2(v2 - lse, v3 - lse);
            }
        }
}

extern "C" void kernel_launch(void* const* d_in, const int* in_sizes, int n_in,
                              void* d_out, int out_size) {
    const float* x = (const float*)d_in[0];   // (B,1,28,28) fp32
    const float* W = (const float*)d_in[1];   // (10,784)    fp32
    const float* b = (const float*)d_in[2];   // (10,)       fp32
    float* out = (float*)d_out;               // (B,10)      fp32

    int batch = in_sizes[0] / 784;

    prep_w<<<(NCHUNK * 16 * 64 + 255) / 256, 256>>>(W);

    int grid = (batch + IMG_BLK - 1) / IMG_BLK;
    cudaFuncSetAttribute(quanv_hmma, cudaFuncAttributeMaxDynamicSharedMemorySize, SMEM_REQ);
    quanv_hmma<<<grid, THREADS, SMEM_REQ>>>(x, b, out, batch);
}